// round 5
// baseline (speedup 1.0000x reference)
#include <cuda_runtime.h>

// Problem constants (fixed-shape problem; grids still derived from in_sizes).
#define MAX_NODES 50000
#define CAP       128           // bucket capacity per node; P(deg>=128) ~ e^-150

// ---------------- device scratch (no allocations allowed) ----------------
__device__ int   g_deg[MAX_NODES];
__device__ int   g_bucket[MAX_NODES * CAP];     // 25.6 MB
__device__ float g_mean[MAX_NODES * 64];        // 12.8 MB
__device__ float g_Bt[128 * 128];               // combined [W_l;W_r] transposed: Bt[k][n]

// ---------------- kernel 1: zero in-degree counters ----------------
__global__ void k_zero_deg(int nN) {
    int i = blockIdx.x * blockDim.x + threadIdx.x;
    if (i < nN) g_deg[i] = 0;
}

// ---------------- kernel 2: bucket fill (CSR-lite, no scan) ----------------
// edge_index is INT32 on device (JAX default x64-disabled downcasts int64).
__global__ void k_fill_buckets(const int* __restrict__ ei, int nE, int nN) {
    int e = blockIdx.x * blockDim.x + threadIdx.x;
    if (e >= nE) return;
    int s = ei[e];               // src row   (edge_index[0][e])
    int d = ei[nE + e];          // dst row   (edge_index[1][e])
    if ((unsigned)s >= (unsigned)nN || (unsigned)d >= (unsigned)nN) return;
    int slot = atomicAdd(&g_deg[d], 1);
    if (slot < CAP) g_bucket[d * CAP + slot] = s;
}

// ---------------- kernel 3: build transposed combined weight ----------------
// Bt[k][n] = (k<64) ? W_l[n][k] : W_r[n][k-64]
__global__ void k_transpose_W(const float* __restrict__ W_l,
                              const float* __restrict__ W_r) {
    int i = blockIdx.x * blockDim.x + threadIdx.x;
    if (i >= 128 * 128) return;
    int k = i & 127;
    int n = i >> 7;
    float v = (k < 64) ? W_l[n * 64 + k] : W_r[n * 64 + (k - 64)];
    g_Bt[k * 128 + n] = v;
}

// ---------------- kernel 4: mean aggregation (one warp per node) ----------------
__global__ void k_aggregate(const float* __restrict__ x, int nN) {
    int gwarp = (blockIdx.x * blockDim.x + threadIdx.x) >> 5;
    int lane  = threadIdx.x & 31;
    if (gwarp >= nN) return;
    int node = gwarp;
    int deg  = g_deg[node];
    int m    = min(deg, CAP);

    const float2* __restrict__ x2 = (const float2*)x;   // 64 f32 = 32 float2 per row
    const int* __restrict__ bkt = &g_bucket[node * CAP];

    float2 acc = make_float2(0.f, 0.f);
    for (int base = 0; base < m; base += 32) {
        int cnt = min(32, m - base);
        int sid = (lane < cnt) ? bkt[base + lane] : 0;
        #pragma unroll 4
        for (int j = 0; j < cnt; j++) {
            int s = __shfl_sync(0xffffffffu, sid, j);
            float2 v = x2[(size_t)s * 32 + lane];       // warp reads full 256B row
            acc.x += v.x;
            acc.y += v.y;
        }
    }
    float inv = 1.0f / fmaxf((float)deg, 1.0f);
    acc.x *= inv;
    acc.y *= inv;
    ((float2*)g_mean)[(size_t)node * 32 + lane] = acc;
}

// ---------------- kernel 5: fused GEMM + bias ----------------
// out[m, n] = sum_k A[m,k] * Bt[k,n] + b_l[n],   A = [mean || x] (K=128)
// Tile: 64 nodes x 128 outs per block, 256 threads, each thread 8x4 accumulators.
__global__ void k_gemm(const float* __restrict__ x,
                       const float* __restrict__ b_l,
                       float* __restrict__ out, int nN) {
    extern __shared__ float smem[];
    float* A_s = smem;              // [64][128]   32 KB
    float* B_s = smem + 64 * 128;   // [128][128]  64 KB (k-major)

    int tid    = threadIdx.x;
    int blockM = blockIdx.x * 64;

    // --- stage A tile: A[m][0:64]=mean row, A[m][64:128]=x row (float4 copies) ---
    const float4* __restrict__ mean4 = (const float4*)g_mean;
    const float4* __restrict__ x4    = (const float4*)x;
    float4* A4s = (float4*)A_s;
    #pragma unroll
    for (int i = tid; i < 64 * 32; i += 256) {
        int mrow = i >> 5;          // 0..63
        int q    = i & 31;          // float4 index within 128-float row
        int gm   = blockM + mrow;
        float4 v = make_float4(0.f, 0.f, 0.f, 0.f);
        if (gm < nN)
            v = (q < 16) ? mean4[(size_t)gm * 16 + q]
                         : x4[(size_t)gm * 16 + (q - 16)];
        A4s[i] = v;
    }

    // --- stage B tile (identical for all blocks; L2-resident after first wave) ---
    float4* B4s = (float4*)B_s;
    const float4* __restrict__ Bt4 = (const float4*)g_Bt;
    #pragma unroll
    for (int i = tid; i < 128 * 32; i += 256) B4s[i] = Bt4[i];
    __syncthreads();

    int tx = tid & 31;              // output group: n0 = tx*4 (0..124)
    int ty = tid >> 5;              // node group:   m0 = ty*8
    int n0 = tx * 4;
    int m0 = ty * 8;

    float acc[8][4];
    float4 bias = *(const float4*)&b_l[n0];
    #pragma unroll
    for (int i = 0; i < 8; i++) {
        acc[i][0] = bias.x; acc[i][1] = bias.y;
        acc[i][2] = bias.z; acc[i][3] = bias.w;
    }

    // Inner: per 4 k-steps, 12 LDS (8 broadcast A.128 + 4 conflict-free B.128), 128 FFMA.
    #pragma unroll 2
    for (int k = 0; k < 128; k += 4) {
        float4 bq0 = B4s[(k + 0) * 32 + tx];
        float4 bq1 = B4s[(k + 1) * 32 + tx];
        float4 bq2 = B4s[(k + 2) * 32 + tx];
        float4 bq3 = B4s[(k + 3) * 32 + tx];
        #pragma unroll
        for (int i = 0; i < 8; i++) {
            float4 a = A4s[(m0 + i) * 32 + (k >> 2)];   // warp-broadcast
            acc[i][0] = fmaf(a.x, bq0.x, acc[i][0]);
            acc[i][1] = fmaf(a.x, bq0.y, acc[i][1]);
            acc[i][2] = fmaf(a.x, bq0.z, acc[i][2]);
            acc[i][3] = fmaf(a.x, bq0.w, acc[i][3]);
            acc[i][0] = fmaf(a.y, bq1.x, acc[i][0]);
            acc[i][1] = fmaf(a.y, bq1.y, acc[i][1]);
            acc[i][2] = fmaf(a.y, bq1.z, acc[i][2]);
            acc[i][3] = fmaf(a.y, bq1.w, acc[i][3]);
            acc[i][0] = fmaf(a.z, bq2.x, acc[i][0]);
            acc[i][1] = fmaf(a.z, bq2.y, acc[i][1]);
            acc[i][2] = fmaf(a.z, bq2.z, acc[i][2]);
            acc[i][3] = fmaf(a.z, bq2.w, acc[i][3]);
            acc[i][0] = fmaf(a.w, bq3.x, acc[i][0]);
            acc[i][1] = fmaf(a.w, bq3.y, acc[i][1]);
            acc[i][2] = fmaf(a.w, bq3.z, acc[i][2]);
            acc[i][3] = fmaf(a.w, bq3.w, acc[i][3]);
        }
    }

    #pragma unroll
    for (int i = 0; i < 8; i++) {
        int gm = blockM + m0 + i;
        if (gm < nN) {
            float4 r = make_float4(acc[i][0], acc[i][1], acc[i][2], acc[i][3]);
            *(float4*)&out[(size_t)gm * 128 + n0] = r;
        }
    }
}

// ---------------- launch ----------------
extern "C" void kernel_launch(void* const* d_in, const int* in_sizes, int n_in,
                              void* d_out, int out_size) {
    const float* x   = (const float*)d_in[0];       // [N, 64]
    const int*   ei  = (const int*)d_in[1];         // [2, E] int32 (JAX x64 off)
    const float* W_l = (const float*)d_in[2];       // [128, 64]
    const float* b_l = (const float*)d_in[3];       // [128]
    const float* W_r = (const float*)d_in[4];       // [128, 64]
    float*       out = (float*)d_out;               // [N, 128]

    int nN = in_sizes[0] / 64;
    int nE = in_sizes[1] / 2;

    k_zero_deg<<<(nN + 255) / 256, 256>>>(nN);
    k_fill_buckets<<<(nE + 255) / 256, 256>>>(ei, nE, nN);
    k_transpose_W<<<(128 * 128 + 255) / 256, 256>>>(W_l, W_r);
    k_aggregate<<<(nN + 7) / 8, 256>>>(x, nN);

    int smem_bytes = (64 * 128 + 128 * 128) * sizeof(float);   // 98304
    cudaFuncSetAttribute(k_gemm, cudaFuncAttributeMaxDynamicSharedMemorySize,
                         smem_bytes);
    k_gemm<<<(nN + 63) / 64, 256, smem_bytes>>>(x, b_l, out, nN);
}

// round 6
// speedup vs baseline: 1.0728x; 1.0728x over previous
#include <cuda_runtime.h>

// Problem constants (fixed-shape problem; grids still derived from in_sizes).
#define MAX_NODES 50000
#define CAP       128           // bucket capacity per node; P(deg>=128) ~ e^-150

// ---------------- device scratch (no allocations allowed) ----------------
__device__ int   g_deg[MAX_NODES];
__device__ int   g_bucket[MAX_NODES * CAP];     // 25.6 MB
__device__ float g_mean[MAX_NODES * 64];        // 12.8 MB
__device__ float g_Bt[128 * 128];               // combined [W_l;W_r] transposed: Bt[k][n]

// ---------------- packed f32x2 helpers (Blackwell) ----------------
#define FMA_F32X2(d, a, b) \
    asm("fma.rn.f32x2 %0, %1, %2, %0;" : "+l"(d) : "l"(a), "l"(b))
#define PACK_DUP_F32X2(out, s) \
    asm("mov.b64 %0, {%1, %1};" : "=l"(out) : "f"(s))
#define PACK_F32X2(out, lo, hi) \
    asm("mov.b64 %0, {%1, %2};" : "=l"(out) : "f"(lo), "f"(hi))
#define UNPACK_F32X2(lo, hi, in) \
    asm("mov.b64 {%0, %1}, %2;" : "=f"(lo), "=f"(hi) : "l"(in))

// ---------------- kernel 1: zero degrees + transpose weights (merged) ----------------
// Bt[k][n] = (k<64) ? W_l[n][k] : W_r[n][k-64]
__global__ void k_init(const float* __restrict__ W_l,
                       const float* __restrict__ W_r, int nN) {
    int i = blockIdx.x * blockDim.x + threadIdx.x;
    if (i < nN) g_deg[i] = 0;
    if (i < 128 * 128) {
        int k = i & 127;
        int n = i >> 7;
        float v = (k < 64) ? W_l[n * 64 + k] : W_r[n * 64 + (k - 64)];
        g_Bt[k * 128 + n] = v;
    }
}

// ---------------- kernel 2: bucket fill (CSR-lite, no scan) ----------------
// edge_index is INT32 on device (JAX default x64-disabled downcasts int64).
__global__ void k_fill_buckets(const int* __restrict__ ei, int nE, int nN) {
    int e = blockIdx.x * blockDim.x + threadIdx.x;
    if (e >= nE) return;
    int s = ei[e];               // src row   (edge_index[0][e])
    int d = ei[nE + e];          // dst row   (edge_index[1][e])
    if ((unsigned)s >= (unsigned)nN || (unsigned)d >= (unsigned)nN) return;
    int slot = atomicAdd(&g_deg[d], 1);
    if (slot < CAP) g_bucket[d * CAP + slot] = s;
}

// ---------------- kernel 3: mean aggregation ----------------
// One warp per node. Two neighbors per warp iteration:
// lanes 0-15 read float4 of neighbor (2p), lanes 16-31 of neighbor (2p+1).
__global__ void k_aggregate(const float* __restrict__ x, int nN) {
    int gwarp = (blockIdx.x * blockDim.x + threadIdx.x) >> 5;
    int lane  = threadIdx.x & 31;
    if (gwarp >= nN) return;
    int node = gwarp;
    int deg  = g_deg[node];
    int m    = min(deg, CAP);

    const float4* __restrict__ x4 = (const float4*)x;   // 64 f32 = 16 float4 per row
    const int* __restrict__ bkt = &g_bucket[node * CAP];

    int col  = lane & 15;
    int half = lane >> 4;

    float4 acc = make_float4(0.f, 0.f, 0.f, 0.f);
    for (int base = 0; base < m; base += 32) {
        int cnt = min(32, m - base);
        int sid = (lane < cnt) ? bkt[base + lane] : -1;
        int pairs = (cnt + 1) >> 1;
        #pragma unroll 4
        for (int p = 0; p < pairs; p++) {
            int s = __shfl_sync(0xffffffffu, sid, 2 * p + half);
            if (s >= 0) {
                float4 v = x4[(size_t)s * 16 + col];    // half-warp reads 256B row
                acc.x += v.x; acc.y += v.y;
                acc.z += v.z; acc.w += v.w;
            }
        }
    }
    // combine the two half-warp partial sums
    acc.x += __shfl_xor_sync(0xffffffffu, acc.x, 16);
    acc.y += __shfl_xor_sync(0xffffffffu, acc.y, 16);
    acc.z += __shfl_xor_sync(0xffffffffu, acc.z, 16);
    acc.w += __shfl_xor_sync(0xffffffffu, acc.w, 16);

    if (half == 0) {
        float inv = 1.0f / fmaxf((float)deg, 1.0f);
        acc.x *= inv; acc.y *= inv; acc.z *= inv; acc.w *= inv;
        ((float4*)g_mean)[(size_t)node * 16 + col] = acc;
    }
}

// ---------------- kernel 4: fused GEMM + bias (packed f32x2 FMA) ----------------
// out[m, n] = sum_k A[m,k] * Bt[k,n] + b_l[n],   A = [mean || x] (K=128)
// Tile: 64 nodes x 128 outs per block, 256 threads, each thread 8x4 accumulators
// held as 8x2 packed f32x2 registers.
__global__ void __launch_bounds__(256, 2)
k_gemm(const float* __restrict__ x,
       const float* __restrict__ b_l,
       float* __restrict__ out, int nN) {
    extern __shared__ float smem[];
    float* A_s = smem;              // [64][128]   32 KB
    float* B_s = smem + 64 * 128;   // [128][128]  64 KB (k-major)

    int tid    = threadIdx.x;
    int blockM = blockIdx.x * 64;

    // --- stage A tile: A[m][0:64]=mean row, A[m][64:128]=x row (float4 copies) ---
    const float4* __restrict__ mean4 = (const float4*)g_mean;
    const float4* __restrict__ x4    = (const float4*)x;
    float4* A4s = (float4*)A_s;
    #pragma unroll
    for (int i = tid; i < 64 * 32; i += 256) {
        int mrow = i >> 5;          // 0..63
        int q    = i & 31;          // float4 index within 128-float row
        int gm   = blockM + mrow;
        float4 v = make_float4(0.f, 0.f, 0.f, 0.f);
        if (gm < nN)
            v = (q < 16) ? mean4[(size_t)gm * 16 + q]
                         : x4[(size_t)gm * 16 + (q - 16)];
        A4s[i] = v;
    }

    // --- stage B tile (identical for all blocks; L2-resident after first wave) ---
    float4* B4s = (float4*)B_s;
    const float4* __restrict__ Bt4 = (const float4*)g_Bt;
    #pragma unroll
    for (int i = tid; i < 128 * 32; i += 256) B4s[i] = Bt4[i];
    __syncthreads();

    int tx = tid & 31;              // output group: n0 = tx*4 (0..124)
    int ty = tid >> 5;              // node group:   m0 = ty*8
    int n0 = tx * 4;
    int m0 = ty * 8;

    const ulonglong2* __restrict__ B8 = (const ulonglong2*)B_s;  // 4 floats / elem

    // packed accumulators: acc01[i] = (out[n0], out[n0+1]), acc23 = (n0+2, n0+3)
    unsigned long long acc01[8], acc23[8];
    {
        float4 bias = *(const float4*)&b_l[n0];
        unsigned long long b01, b23;
        PACK_F32X2(b01, bias.x, bias.y);
        PACK_F32X2(b23, bias.z, bias.w);
        #pragma unroll
        for (int i = 0; i < 8; i++) { acc01[i] = b01; acc23[i] = b23; }
    }

    // Inner: per 4 k-steps & 8 rows -> 64 FMA2 (fma pipe) + 32 dup-packs (alu pipe).
    #pragma unroll 2
    for (int k = 0; k < 128; k += 4) {
        ulonglong2 b0 = B8[(k + 0) * 32 + tx];
        ulonglong2 b1 = B8[(k + 1) * 32 + tx];
        ulonglong2 b2 = B8[(k + 2) * 32 + tx];
        ulonglong2 b3 = B8[(k + 3) * 32 + tx];
        #pragma unroll
        for (int i = 0; i < 8; i++) {
            float4 a = A4s[(m0 + i) * 32 + (k >> 2)];   // warp-broadcast LDS.128
            unsigned long long ap;
            PACK_DUP_F32X2(ap, a.x);
            FMA_F32X2(acc01[i], ap, b0.x);
            FMA_F32X2(acc23[i], ap, b0.y);
            PACK_DUP_F32X2(ap, a.y);
            FMA_F32X2(acc01[i], ap, b1.x);
            FMA_F32X2(acc23[i], ap, b1.y);
            PACK_DUP_F32X2(ap, a.z);
            FMA_F32X2(acc01[i], ap, b2.x);
            FMA_F32X2(acc23[i], ap, b2.y);
            PACK_DUP_F32X2(ap, a.w);
            FMA_F32X2(acc01[i], ap, b3.x);
            FMA_F32X2(acc23[i], ap, b3.y);
        }
    }

    #pragma unroll
    for (int i = 0; i < 8; i++) {
        int gm = blockM + m0 + i;
        if (gm < nN) {
            float4 r;
            UNPACK_F32X2(r.x, r.y, acc01[i]);
            UNPACK_F32X2(r.z, r.w, acc23[i]);
            *(float4*)&out[(size_t)gm * 128 + n0] = r;
        }
    }
}

// ---------------- launch ----------------
extern "C" void kernel_launch(void* const* d_in, const int* in_sizes, int n_in,
                              void* d_out, int out_size) {
    const float* x   = (const float*)d_in[0];       // [N, 64]
    const int*   ei  = (const int*)d_in[1];         // [2, E] int32 (JAX x64 off)
    const float* W_l = (const float*)d_in[2];       // [128, 64]
    const float* b_l = (const float*)d_in[3];       // [128]
    const float* W_r = (const float*)d_in[4];       // [128, 64]
    float*       out = (float*)d_out;               // [N, 128]

    int nN = in_sizes[0] / 64;
    int nE = in_sizes[1] / 2;

    int initN = (nN > 128 * 128) ? nN : 128 * 128;
    k_init<<<(initN + 255) / 256, 256>>>(W_l, W_r, nN);
    k_fill_buckets<<<(nE + 255) / 256, 256>>>(ei, nE, nN);
    k_aggregate<<<(nN + 7) / 8, 256>>>(x, nN);

    int smem_bytes = (64 * 128 + 128 * 128) * sizeof(float);   // 98304
    cudaFuncSetAttribute(k_gemm, cudaFuncAttributeMaxDynamicSharedMemorySize,
                         smem_bytes);
    k_gemm<<<(nN + 63) / 64, 256, smem_bytes>>>(x, b_l, out, nN);
}